// round 15
// baseline (speedup 1.0000x reference)
#include <cuda_runtime.h>
#include <cuda_bf16.h>
#include <cuda_fp16.h>
#include <math.h>
#include <stdint.h>

#define B_  4
#define S_  2048
#define D_  1024
#define H_  16
#define HD_ 64
#define M_  (B_*S_)   // 8192 tokens

// ---------------------------------------------------------------------------
// Scratch (device globals; no runtime allocation)
// ---------------------------------------------------------------------------
__device__ __half g_xf[M_*D_];                          // x fp16 [M][D]
__device__ __half g_wf[4*D_*D_];                        // Wq,Wk,Wv,Wo fp16 [N][K]
__device__ __half g_qf[M_*D_];                          // q/k/v fp16 [BH][S][HD]
__device__ __half g_kf[M_*D_];
__device__ __half g_vf[M_*D_];
__device__ __half g_af[M_*D_];                          // attn out fp16 [M][D]
__device__ float g_y[M_*D_];                            // pre-LN fp32

// ---------------------------------------------------------------------------
// Helpers
// ---------------------------------------------------------------------------
__device__ __forceinline__ uint32_t packhf(float a, float b) {
    __half2 t = __floats2half2_rn(a, b);
    return *reinterpret_cast<uint32_t*>(&t);
}
__device__ __forceinline__ float ex2f(float x) {
    float r;
    asm("ex2.approx.f32 %0, %1;" : "=f"(r) : "f"(x));
    return r;
}
__device__ __forceinline__ void ldsm4(uint32_t& r0, uint32_t& r1, uint32_t& r2, uint32_t& r3,
                                      uint32_t a) {
    asm volatile("ldmatrix.sync.aligned.m8n8.x4.shared.b16 {%0,%1,%2,%3},[%4];"
                 : "=r"(r0), "=r"(r1), "=r"(r2), "=r"(r3) : "r"(a));
}
__device__ __forceinline__ void ldsm4t(uint32_t& r0, uint32_t& r1, uint32_t& r2, uint32_t& r3,
                                       uint32_t a) {
    asm volatile("ldmatrix.sync.aligned.m8n8.x4.trans.shared.b16 {%0,%1,%2,%3},[%4];"
                 : "=r"(r0), "=r"(r1), "=r"(r2), "=r"(r3) : "r"(a));
}
__device__ __forceinline__ void mma16816h(float* d, const uint32_t* a, const uint32_t* b) {
    asm volatile(
        "mma.sync.aligned.m16n8k16.row.col.f32.f16.f16.f32 "
        "{%0,%1,%2,%3},{%4,%5,%6,%7},{%8,%9},{%0,%1,%2,%3};"
        : "+f"(d[0]), "+f"(d[1]), "+f"(d[2]), "+f"(d[3])
        : "r"(a[0]), "r"(a[1]), "r"(a[2]), "r"(a[3]), "r"(b[0]), "r"(b[1]));
}
__device__ __forceinline__ void cpasync16(uint32_t dst, const void* src) {
    asm volatile("cp.async.cg.shared.global [%0], [%1], 16;" :: "r"(dst), "l"(src));
}
__device__ __forceinline__ void cp_commit() {
    asm volatile("cp.async.commit_group;" ::: "memory");
}
template<int N> __device__ __forceinline__ void cp_wait() {
    asm volatile("cp.async.wait_group %0;" :: "n"(N) : "memory");
}
__device__ __forceinline__ uint32_t smem_u32(const void* p) {
    return (uint32_t)__cvta_generic_to_shared(p);
}

// ---------------------------------------------------------------------------
// Conversion kernels
// ---------------------------------------------------------------------------
__global__ void __launch_bounds__(256) tof16_kernel(const float* __restrict__ src,
                                                    __half* __restrict__ dst, int n4)
{
    int i = blockIdx.x * 256 + threadIdx.x;
    if (i >= n4) return;
    float4 v = ((const float4*)src)[i];
    ((__half2*)dst)[i*2]   = __floats2half2_rn(v.x, v.y);
    ((__half2*)dst)[i*2+1] = __floats2half2_rn(v.z, v.w);
}

__global__ void __launch_bounds__(256) splitw_kernel(const float* __restrict__ w0,
                                                     const float* __restrict__ w1,
                                                     const float* __restrict__ w2,
                                                     const float* __restrict__ w3)
{
    const int wsel = blockIdx.y;
    const float* src = (wsel == 0) ? w0 : (wsel == 1) ? w1 : (wsel == 2) ? w2 : w3;
    __half* dst = g_wf + (size_t)wsel * D_ * D_;
    int i = blockIdx.x * 256 + threadIdx.x;
    float4 v = ((const float4*)src)[i];
    ((__half2*)dst)[i*2]   = __floats2half2_rn(v.x, v.y);
    ((__half2*)dst)[i*2+1] = __floats2half2_rn(v.z, v.w);
}

// ---------------------------------------------------------------------------
// 1x-fp16 GEMM, CTA tile 128m x 128n, BK=32, 8 warps (warp 32m x 64n).
// 2-stage cp.async; 32KB static smem. QKV merged via blockIdx.z (mode 0/1/2);
// smem rows: 32 k = 64B = 4 chunks, swizzle ck^((row>>1)&3).
// ---------------------------------------------------------------------------
__global__ void __launch_bounds__(256) gemm_f16(const __half* __restrict__ X,
                                                const float* __restrict__ bq,
                                                const float* __restrict__ bk,
                                                const float* __restrict__ bv)
{
    __shared__ __align__(16) __half sA[2][128*32];   // 8KB/stage
    __shared__ __align__(16) __half sB[2][128*32];   // 8KB/stage

    const int mode = blockIdx.z;
    const __half* W = g_wf + (size_t)mode * D_ * D_;
    const float* bias = (mode == 0) ? bq : (mode == 1) ? bk : bv;

    const int bm = blockIdx.y * 128, bn = blockIdx.x * 128;
    const int tid = threadIdx.x, wid = tid >> 5, lane = tid & 31;
    const int lg = lane >> 2, lc = lane & 3;
    const int wm = (wid >> 1) * 32;   // 0/32/64/96
    const int wn = (wid & 1) * 64;    // 0/64

    const uint32_t sAb = smem_u32(sA);
    const uint32_t sBb = smem_u32(sB);

    auto prefetch = [&](int k0, int st) {
        const uint32_t a_st = sAb + st * 8192;
        const uint32_t b_st = sBb + st * 8192;
#pragma unroll
        for (int i = 0; i < 2; i++) {            // A: 512 chunks, 2/thread
            const int cid = tid + i * 256;
            const int row = cid >> 2, ck = cid & 3;
            const uint32_t so = row * 64 + ((ck ^ ((row >> 1) & 3)) * 16);
            cpasync16(a_st + so, X + (size_t)(bm + row) * D_ + k0 + ck * 8);
        }
#pragma unroll
        for (int i = 0; i < 2; i++) {            // B: 512 chunks, 2/thread
            const int cid = tid + i * 256;
            const int row = cid >> 2, ck = cid & 3;
            const uint32_t so = row * 64 + ((ck ^ ((row >> 1) & 3)) * 16);
            cpasync16(b_st + so, W + (size_t)(bn + row) * D_ + k0 + ck * 8);
        }
    };

    float acc[2][8][4] = {};

    prefetch(0, 0); cp_commit();

    const int NIT = D_ / 32;   // 32
    for (int it = 0; it < NIT; it++) {
        if (it + 1 < NIT) { prefetch((it + 1) * 32, (it + 1) & 1); cp_commit(); }
        if (it + 1 < NIT) cp_wait<1>(); else cp_wait<0>();
        __syncthreads();

        const int st = it & 1;
        const uint32_t sA0 = sAb + st * 8192;
        const uint32_t sB0 = sBb + st * 8192;

#pragma unroll
        for (int ks = 0; ks < 2; ks++) {
            uint32_t af[2][4];
            uint32_t bf[8][2];
#pragma unroll
            for (int ms = 0; ms < 2; ms++) {
                const int row = wm + ms * 16 + (lane & 15);
                const int ck = ks * 2 + (lane >> 4);
                const uint32_t off = row * 64 + ((ck ^ ((row >> 1) & 3)) * 16);
                ldsm4(af[ms][0], af[ms][1], af[ms][2], af[ms][3], sA0 + off);
            }
#pragma unroll
            for (int np = 0; np < 4; np++) {
                const int n = wn + np * 16 + (lane & 7) + ((lane >> 4) << 3);
                const int ck = ks * 2 + ((lane >> 3) & 1);
                const uint32_t off = n * 64 + ((ck ^ ((n >> 1) & 3)) * 16);
                ldsm4(bf[2*np][0], bf[2*np][1], bf[2*np+1][0], bf[2*np+1][1], sB0 + off);
            }
#pragma unroll
            for (int ms = 0; ms < 2; ms++)
#pragma unroll
                for (int ns = 0; ns < 8; ns++)
                    mma16816h(acc[ms][ns], af[ms], bf[ns]);
        }
        __syncthreads();
    }

    __half* outf = (mode == 0) ? g_qf : (mode == 1) ? g_kf : g_vf;
#pragma unroll
    for (int ms = 0; ms < 2; ms++)
#pragma unroll
        for (int ns = 0; ns < 8; ns++) {
            const int col = bn + wn + ns * 8 + lc * 2;
            const float2 bz = *(const float2*)&bias[col];
#pragma unroll
            for (int hr = 0; hr < 2; hr++) {
                const int row = bm + wm + ms * 16 + lg + hr * 8;
                const float v0 = acc[ms][ns][hr*2+0] + bz.x;
                const float v1 = acc[ms][ns][hr*2+1] + bz.y;
                const int b = row >> 11, s = row & 2047;
                const int h = col >> 6, hd = col & 63;
                const size_t o = (((size_t)(b * H_ + h)) * S_ + s) * HD_ + hd;
                *(__half2*)&outf[o] = __floats2half2_rn(v0, v1);
            }
        }
}

// ---------------------------------------------------------------------------
// 1x-fp16 GEMM for Wo (same 128x128 tiling): y = A @ Wo^T + bias + resid.
// ---------------------------------------------------------------------------
__global__ void __launch_bounds__(256) gemm_wo(const __half* __restrict__ A,
                                               const __half* __restrict__ W,
                                               const float* __restrict__ bias,
                                               const float* __restrict__ resid)
{
    __shared__ __align__(16) __half sA[2][128*32];
    __shared__ __align__(16) __half sB[2][128*32];

    const int bm = blockIdx.y * 128, bn = blockIdx.x * 128;
    const int tid = threadIdx.x, wid = tid >> 5, lane = tid & 31;
    const int lg = lane >> 2, lc = lane & 3;
    const int wm = (wid >> 1) * 32;
    const int wn = (wid & 1) * 64;

    const uint32_t sAb = smem_u32(sA);
    const uint32_t sBb = smem_u32(sB);

    auto prefetch = [&](int k0, int st) {
        const uint32_t a_st = sAb + st * 8192;
        const uint32_t b_st = sBb + st * 8192;
#pragma unroll
        for (int i = 0; i < 2; i++) {
            const int cid = tid + i * 256;
            const int row = cid >> 2, ck = cid & 3;
            const uint32_t so = row * 64 + ((ck ^ ((row >> 1) & 3)) * 16);
            cpasync16(a_st + so, A + (size_t)(bm + row) * D_ + k0 + ck * 8);
        }
#pragma unroll
        for (int i = 0; i < 2; i++) {
            const int cid = tid + i * 256;
            const int row = cid >> 2, ck = cid & 3;
            const uint32_t so = row * 64 + ((ck ^ ((row >> 1) & 3)) * 16);
            cpasync16(b_st + so, W + (size_t)(bn + row) * D_ + k0 + ck * 8);
        }
    };

    float acc[2][8][4] = {};

    prefetch(0, 0); cp_commit();

    const int NIT = D_ / 32;   // 32
    for (int it = 0; it < NIT; it++) {
        if (it + 1 < NIT) { prefetch((it + 1) * 32, (it + 1) & 1); cp_commit(); }
        if (it + 1 < NIT) cp_wait<1>(); else cp_wait<0>();
        __syncthreads();

        const int st = it & 1;
        const uint32_t sA0 = sAb + st * 8192;
        const uint32_t sB0 = sBb + st * 8192;

#pragma unroll
        for (int ks = 0; ks < 2; ks++) {
            uint32_t af[2][4];
            uint32_t bf[8][2];
#pragma unroll
            for (int ms = 0; ms < 2; ms++) {
                const int row = wm + ms * 16 + (lane & 15);
                const int ck = ks * 2 + (lane >> 4);
                const uint32_t off = row * 64 + ((ck ^ ((row >> 1) & 3)) * 16);
                ldsm4(af[ms][0], af[ms][1], af[ms][2], af[ms][3], sA0 + off);
            }
#pragma unroll
            for (int np = 0; np < 4; np++) {
                const int n = wn + np * 16 + (lane & 7) + ((lane >> 4) << 3);
                const int ck = ks * 2 + ((lane >> 3) & 1);
                const uint32_t off = n * 64 + ((ck ^ ((n >> 1) & 3)) * 16);
                ldsm4(bf[2*np][0], bf[2*np][1], bf[2*np+1][0], bf[2*np+1][1], sB0 + off);
            }
#pragma unroll
            for (int ms = 0; ms < 2; ms++)
#pragma unroll
                for (int ns = 0; ns < 8; ns++)
                    mma16816h(acc[ms][ns], af[ms], bf[ns]);
        }
        __syncthreads();
    }

    // epilogue: y = C + bias + resid (fp32)
#pragma unroll
    for (int ms = 0; ms < 2; ms++)
#pragma unroll
        for (int ns = 0; ns < 8; ns++) {
            const int col = bn + wn + ns * 8 + lc * 2;
            const float2 bz = *(const float2*)&bias[col];
#pragma unroll
            for (int hr = 0; hr < 2; hr++) {
                const int row = bm + wm + ms * 16 + lg + hr * 8;
                const size_t o = (size_t)row * D_ + col;
                const float2 rr = *(const float2*)&resid[o];
                float2 w;
                w.x = acc[ms][ns][hr*2+0] + bz.x + rr.x;
                w.y = acc[ms][ns][hr*2+1] + bz.y + rr.y;
                *(float2*)&g_y[o] = w;
            }
        }
}

// ---------------------------------------------------------------------------
// 1x-fp16 flash attention (R14 config); ex2-based softmax (log2e folded);
// two 32-token half-passes; lane-partial lrow; single-fp16 output.
// dyn smem: sK 2x8KB + sV 2x8KB + maskf 8KB = 40960 B.
// ---------------------------------------------------------------------------
#define SCALE_LOG2E 0.18033688011112042f   // 0.125 * log2(e)

__global__ void __launch_bounds__(128) attn_f16(const int* __restrict__ mask)
{
    extern __shared__ __align__(16) char dynsm[];
    __half* sK = (__half*)dynsm;                    // [2][64*64]
    __half* sV = (__half*)(dynsm + 16384);          // [2][64*64]
    float* smf = (float*)(dynsm + 32768);           // [2048] additive mask (log2 dom.)

    const int bh = blockIdx.y, b = bh >> 4, h = bh & 15;
    const int q0 = blockIdx.x * 64;
    const int tid = threadIdx.x, wid = tid >> 5, lane = tid & 31;
    const int lg = lane >> 2, lc = lane & 3;

    const size_t base = (size_t)bh * S_ * HD_;
    const __half* Qf = g_qf + base;
    const __half* Kf = g_kf + base;
    const __half* Vf = g_vf + base;

    const uint32_t sKb = smem_u32(sK);
    const uint32_t sVb = smem_u32(sV);

    // ---- preload additive mask: 0 or -10000*log2(e) ----
#pragma unroll
    for (int i = 0; i < 4; i++) {
        const int idx = tid + i * 128;
        int4 m = ((const int4*)(mask + b * S_))[idx];
        float4 f;
        f.x = m.x ? 0.f : -14426.95f;
        f.y = m.y ? 0.f : -14426.95f;
        f.z = m.z ? 0.f : -14426.95f;
        f.w = m.w ? 0.f : -14426.95f;
        ((float4*)smf)[idx] = f;
    }

    // ---- stage Q in sK stage0, extract fragments ----
#pragma unroll
    for (int i = 0; i < 4; i++) {
        const int cid = tid + i * 128;
        const int row = cid >> 3, ck = cid & 7;
        const size_t go = (size_t)(q0 + row) * HD_ + ck * 8;
        const uint32_t so = row * 128 + ((ck ^ (row & 7)) * 16);
        *(uint4*)((char*)sK + so) = *(const uint4*)(Qf + go);
    }
    __syncthreads();
    uint32_t qf[4][4];
#pragma unroll
    for (int ks = 0; ks < 4; ks++) {
        const int row = wid * 16 + (lane & 15);
        const int ck = ks * 2 + (lane >> 4);
        const uint32_t off = row * 128 + ((ck ^ (row & 7)) * 16);
        ldsm4(qf[ks][0], qf[ks][1], qf[ks][2], qf[ks][3], sKb + off);
    }
    __syncthreads();

    auto prefetch = [&](int kt, int st) {
#pragma unroll
        for (int i = 0; i < 4; i++) {
            const int cid = tid + i * 128;
            const int row = cid >> 3, ck = cid & 7;
            const size_t go = (size_t)(kt + row) * HD_ + ck * 8;
            const uint32_t so = st * 8192 + row * 128 + ((ck ^ (row & 7)) * 16);
            cpasync16(sKb + so, Kf + go);
            cpasync16(sVb + so, Vf + go);
        }
    };

    float accO[8][4] = {};
    float lrow[2] = {0.f, 0.f};   // lane-partial; reduced at epilogue

    prefetch(0, 0); cp_commit();

    const int NIT = S_ / 64;   // 32
    for (int it = 0; it < NIT; it++) {
        const int kt = it * 64;
        if (it + 1 < NIT) { prefetch((it + 1) * 64, (it + 1) & 1); cp_commit(); }
        if (it + 1 < NIT) cp_wait<1>(); else cp_wait<0>();
        __syncthreads();

        const int st = it & 1;
        const uint32_t sK0 = sKb + st * 8192;
        const uint32_t sV0 = sVb + st * 8192;

        // ---- two 32-token half-passes ----
#pragma unroll
        for (int hf = 0; hf < 2; hf++) {
            float s[4][4] = {};
#pragma unroll
            for (int ks = 0; ks < 4; ks++) {
                uint32_t kb[4][2];
#pragma unroll
                for (int np = 0; np < 2; np++) {
                    const int n = hf * 32 + np * 16 + (lane & 7) + ((lane >> 4) << 3);
                    const int ck = ks * 2 + ((lane >> 3) & 1);
                    const uint32_t off = n * 128 + ((ck ^ (n & 7)) * 16);
                    ldsm4(kb[2*np][0], kb[2*np][1], kb[2*np+1][0], kb[2*np+1][1], sK0 + off);
                }
#pragma unroll
                for (int ns = 0; ns < 4; ns++)
                    mma16816h(s[ns], qf[ks], kb[ns]);
            }

#pragma unroll
            for (int r = 0; r < 2; r++) {
                float ls = 0.f;
#pragma unroll
                for (int ns = 0; ns < 4; ns++)
#pragma unroll
                    for (int j = 0; j < 2; j++) {
                        const float madd = smf[kt + hf*32 + ns*8 + lc*2 + j];
                        const float p = ex2f(fmaf(s[ns][r*2+j], SCALE_LOG2E, madd));
                        s[ns][r*2+j] = p;
                        ls += p;
                    }
                lrow[r] += ls;
            }

#pragma unroll
            for (int j = 0; j < 2; j++) {
                uint32_t pa[4];
                pa[0] = packhf(s[2*j][0],   s[2*j][1]);
                pa[1] = packhf(s[2*j][2],   s[2*j][3]);
                pa[2] = packhf(s[2*j+1][0], s[2*j+1][1]);
                pa[3] = packhf(s[2*j+1][2], s[2*j+1][3]);
                uint32_t vb[8][2];
#pragma unroll
                for (int np = 0; np < 4; np++) {
                    const int tok = hf * 32 + j * 16 + (lane & 15);
                    const int ck = np * 2 + (lane >> 4);
                    const uint32_t off = tok * 128 + ((ck ^ (tok & 7)) * 16);
                    ldsm4t(vb[2*np][0], vb[2*np][1], vb[2*np+1][0], vb[2*np+1][1], sV0 + off);
                }
#pragma unroll
                for (int ns = 0; ns < 8; ns++)
                    mma16816h(accO[ns], pa, vb[ns]);
            }
        }
        __syncthreads();
    }

    // ---- epilogue: reduce lrow, normalize, write single fp16 ----
#pragma unroll
    for (int r = 0; r < 2; r++) {
        lrow[r] += __shfl_xor_sync(0xffffffffu, lrow[r], 1);
        lrow[r] += __shfl_xor_sync(0xffffffffu, lrow[r], 2);
    }
    const float inv0 = 1.f / lrow[0];
    const float inv1 = 1.f / lrow[1];
    const int t0 = b * S_ + q0 + wid * 16 + lg;
#pragma unroll
    for (int ns = 0; ns < 8; ns++) {
        const int col = h * 64 + ns * 8 + lc * 2;
        *(__half2*)&g_af[(size_t)t0 * D_ + col] =
            __floats2half2_rn(accO[ns][0] * inv0, accO[ns][1] * inv0);
        *(__half2*)&g_af[(size_t)(t0 + 8) * D_ + col] =
            __floats2half2_rn(accO[ns][2] * inv1, accO[ns][3] * inv1);
    }
}

// ---------------------------------------------------------------------------
// LayerNorm: one warp per token row. 256 threads = 8 rows/block, no barriers.
// ---------------------------------------------------------------------------
__global__ void __launch_bounds__(256) ln_kernel(const float* __restrict__ gamma,
                                                 const float* __restrict__ beta,
                                                 float* __restrict__ out)
{
    const int row = blockIdx.x * 8 + (threadIdx.x >> 5);
    const int lane = threadIdx.x & 31;
    const float4* yr = (const float4*)(g_y + (size_t)row * D_);

    float4 v[8];
    float sum = 0.f, sq = 0.f;
#pragma unroll
    for (int i = 0; i < 8; i++) {
        v[i] = yr[lane + i * 32];
        sum += v[i].x + v[i].y + v[i].z + v[i].w;
        sq  += v[i].x*v[i].x + v[i].y*v[i].y + v[i].z*v[i].z + v[i].w*v[i].w;
    }
#pragma unroll
    for (int off = 16; off; off >>= 1) {
        sum += __shfl_xor_sync(0xffffffffu, sum, off);
        sq  += __shfl_xor_sync(0xffffffffu, sq,  off);
    }
    const float mu   = sum * (1.f / D_);
    const float var  = sq * (1.f / D_) - mu * mu;
    const float rstd = rsqrtf(var + 1e-5f);

    float4* outr = (float4*)(out + (size_t)row * D_);
#pragma unroll
    for (int i = 0; i < 8; i++) {
        const float4 g4 = ((const float4*)gamma)[lane + i * 32];
        const float4 b4 = ((const float4*)beta)[lane + i * 32];
        float4 r;
        r.x = (v[i].x - mu) * rstd * g4.x + b4.x;
        r.y = (v[i].y - mu) * rstd * g4.y + b4.y;
        r.z = (v[i].z - mu) * rstd * g4.z + b4.z;
        r.w = (v[i].w - mu) * rstd * g4.w + b4.w;
        outr[lane + i * 32] = r;
    }
}

// ---------------------------------------------------------------------------
extern "C" void kernel_launch(void* const* d_in, const int* in_sizes, int n_in,
                              void* d_out, int out_size)
{
    const float* x     = (const float*)d_in[0];
    // d_in[1]: template_ids (unused by reference math)
    const int*   mask  = (const int*)  d_in[2];
    const float* Wq    = (const float*)d_in[3];
    const float* bq    = (const float*)d_in[4];
    const float* Wk    = (const float*)d_in[5];
    const float* bk    = (const float*)d_in[6];
    const float* Wv    = (const float*)d_in[7];
    const float* bv    = (const float*)d_in[8];
    const float* Wo    = (const float*)d_in[9];
    const float* bo    = (const float*)d_in[10];
    const float* gamma = (const float*)d_in[11];
    const float* beta  = (const float*)d_in[12];
    float* out = (float*)d_out;

    __half *xf, *wf, *af;
    cudaGetSymbolAddress((void**)&xf, g_xf);
    cudaGetSymbolAddress((void**)&wf, g_wf);
    cudaGetSymbolAddress((void**)&af, g_af);

    tof16_kernel<<<M_*D_/4/256, 256>>>(x, xf, M_*D_/4);
    splitw_kernel<<<dim3(D_*D_/4/256, 4), 256>>>(Wq, Wk, Wv, Wo);

    gemm_f16<<<dim3(D_/128, M_/128, 3), 256>>>(xf, bq, bk, bv);

    const int attn_smem = 40960;
    cudaFuncSetAttribute(attn_f16, cudaFuncAttributeMaxDynamicSharedMemorySize, attn_smem);
    attn_f16<<<dim3(S_/64, B_*H_), 128, attn_smem>>>(mask);

    gemm_wo<<<dim3(D_/128, M_/128), 256>>>(af, wf + 3*(size_t)D_*D_, bo, x);
    ln_kernel<<<M_/8, 256>>>(gamma, beta, out);
}

// round 16
// speedup vs baseline: 1.0218x; 1.0218x over previous
#include <cuda_runtime.h>
#include <cuda_bf16.h>
#include <cuda_fp16.h>
#include <math.h>
#include <stdint.h>

#define B_  4
#define S_  2048
#define D_  1024
#define H_  16
#define HD_ 64
#define M_  (B_*S_)   // 8192 tokens

// ---------------------------------------------------------------------------
// Scratch (device globals; no runtime allocation)
// ---------------------------------------------------------------------------
__device__ __half g_xf[M_*D_];                          // x fp16 [M][D]
__device__ __half g_wf[4*D_*D_];                        // Wq,Wk,Wv,Wo fp16 [N][K]
__device__ __half g_qf[M_*D_];                          // q/k/v fp16 [BH][S][HD]
__device__ __half g_kf[M_*D_];
__device__ __half g_vf[M_*D_];
__device__ __half g_af[M_*D_];                          // attn out fp16 [M][D]
__device__ float g_y[M_*D_];                            // pre-LN fp32

// ---------------------------------------------------------------------------
// Helpers
// ---------------------------------------------------------------------------
__device__ __forceinline__ uint32_t packhf(float a, float b) {
    __half2 t = __floats2half2_rn(a, b);
    return *reinterpret_cast<uint32_t*>(&t);
}
__device__ __forceinline__ float ex2f(float x) {
    float r;
    asm("ex2.approx.f32 %0, %1;" : "=f"(r) : "f"(x));
    return r;
}
__device__ __forceinline__ void ldsm4(uint32_t& r0, uint32_t& r1, uint32_t& r2, uint32_t& r3,
                                      uint32_t a) {
    asm volatile("ldmatrix.sync.aligned.m8n8.x4.shared.b16 {%0,%1,%2,%3},[%4];"
                 : "=r"(r0), "=r"(r1), "=r"(r2), "=r"(r3) : "r"(a));
}
__device__ __forceinline__ void ldsm4t(uint32_t& r0, uint32_t& r1, uint32_t& r2, uint32_t& r3,
                                       uint32_t a) {
    asm volatile("ldmatrix.sync.aligned.m8n8.x4.trans.shared.b16 {%0,%1,%2,%3},[%4];"
                 : "=r"(r0), "=r"(r1), "=r"(r2), "=r"(r3) : "r"(a));
}
__device__ __forceinline__ void mma16816h(float* d, const uint32_t* a, const uint32_t* b) {
    asm volatile(
        "mma.sync.aligned.m16n8k16.row.col.f32.f16.f16.f32 "
        "{%0,%1,%2,%3},{%4,%5,%6,%7},{%8,%9},{%0,%1,%2,%3};"
        : "+f"(d[0]), "+f"(d[1]), "+f"(d[2]), "+f"(d[3])
        : "r"(a[0]), "r"(a[1]), "r"(a[2]), "r"(a[3]), "r"(b[0]), "r"(b[1]));
}
__device__ __forceinline__ void cpasync16(uint32_t dst, const void* src) {
    asm volatile("cp.async.cg.shared.global [%0], [%1], 16;" :: "r"(dst), "l"(src));
}
__device__ __forceinline__ void cp_commit() {
    asm volatile("cp.async.commit_group;" ::: "memory");
}
template<int N> __device__ __forceinline__ void cp_wait() {
    asm volatile("cp.async.wait_group %0;" :: "n"(N) : "memory");
}
__device__ __forceinline__ uint32_t smem_u32(const void* p) {
    return (uint32_t)__cvta_generic_to_shared(p);
}

// ---------------------------------------------------------------------------
// Conversion kernels
// ---------------------------------------------------------------------------
__global__ void __launch_bounds__(256) tof16_kernel(const float* __restrict__ src,
                                                    __half* __restrict__ dst, int n4)
{
    int i = blockIdx.x * 256 + threadIdx.x;
    if (i >= n4) return;
    float4 v = ((const float4*)src)[i];
    ((__half2*)dst)[i*2]   = __floats2half2_rn(v.x, v.y);
    ((__half2*)dst)[i*2+1] = __floats2half2_rn(v.z, v.w);
}

__global__ void __launch_bounds__(256) splitw_kernel(const float* __restrict__ w0,
                                                     const float* __restrict__ w1,
                                                     const float* __restrict__ w2,
                                                     const float* __restrict__ w3)
{
    const int wsel = blockIdx.y;
    const float* src = (wsel == 0) ? w0 : (wsel == 1) ? w1 : (wsel == 2) ? w2 : w3;
    __half* dst = g_wf + (size_t)wsel * D_ * D_;
    int i = blockIdx.x * 256 + threadIdx.x;
    float4 v = ((const float4*)src)[i];
    ((__half2*)dst)[i*2]   = __floats2half2_rn(v.x, v.y);
    ((__half2*)dst)[i*2+1] = __floats2half2_rn(v.z, v.w);
}

// ---------------------------------------------------------------------------
// 1x-fp16 GEMM for Q/K/V projections (R14 config), merged via blockIdx.z.
// CTA 128x64, BK=64, 8 warps (warp 32x32). 2-stage cp.async. 48KB static smem.
// ---------------------------------------------------------------------------
__global__ void __launch_bounds__(256) gemm_f16(const __half* __restrict__ X,
                                                const float* __restrict__ bq,
                                                const float* __restrict__ bk,
                                                const float* __restrict__ bv)
{
    __shared__ __align__(16) __half sA[2][128*64];   // 16KB/stage
    __shared__ __align__(16) __half sB[2][64*64];    // 8KB/stage

    const int mode = blockIdx.z;
    const __half* W = g_wf + (size_t)mode * D_ * D_;
    const float* bias = (mode == 0) ? bq : (mode == 1) ? bk : bv;

    const int bm = blockIdx.y * 128, bn = blockIdx.x * 64;
    const int tid = threadIdx.x, wid = tid >> 5, lane = tid & 31;
    const int lg = lane >> 2, lc = lane & 3;
    const int wm = (wid >> 1) * 32, wn = (wid & 1) * 32;

    const uint32_t sAb = smem_u32(sA);
    const uint32_t sBb = smem_u32(sB);

    auto prefetch = [&](int k0, int st) {
        const uint32_t a_st = sAb + st * 16384;
        const uint32_t b_st = sBb + st * 8192;
#pragma unroll
        for (int i = 0; i < 4; i++) {
            const int cid = tid + i * 256;
            const int row = cid >> 3, ck = cid & 7;
            const uint32_t so = row * 128 + ((ck ^ (row & 7)) * 16);
            cpasync16(a_st + so, X + (size_t)(bm + row) * D_ + k0 + ck * 8);
        }
#pragma unroll
        for (int i = 0; i < 2; i++) {
            const int cid = tid + i * 256;
            const int row = cid >> 3, ck = cid & 7;
            const uint32_t so = row * 128 + ((ck ^ (row & 7)) * 16);
            cpasync16(b_st + so, W + (size_t)(bn + row) * D_ + k0 + ck * 8);
        }
    };

    float acc[2][4][4] = {};

    prefetch(0, 0); cp_commit();

    const int NIT = D_ / 64;   // 16
    for (int it = 0; it < NIT; it++) {
        if (it + 1 < NIT) { prefetch((it + 1) * 64, (it + 1) & 1); cp_commit(); }
        if (it + 1 < NIT) cp_wait<1>(); else cp_wait<0>();
        __syncthreads();

        const int st = it & 1;
        const uint32_t sA0 = sAb + st * 16384;
        const uint32_t sB0 = sBb + st * 8192;

#pragma unroll
        for (int ks = 0; ks < 4; ks++) {
            uint32_t af[2][4];
            uint32_t bf[4][2];
#pragma unroll
            for (int ms = 0; ms < 2; ms++) {
                const int row = wm + ms * 16 + (lane & 15);
                const int ck = ks * 2 + (lane >> 4);
                const uint32_t off = row * 128 + ((ck ^ (row & 7)) * 16);
                ldsm4(af[ms][0], af[ms][1], af[ms][2], af[ms][3], sA0 + off);
            }
#pragma unroll
            for (int np = 0; np < 2; np++) {
                const int n = wn + np * 16 + (lane & 7) + ((lane >> 4) << 3);
                const int ck = ks * 2 + ((lane >> 3) & 1);
                const uint32_t off = n * 128 + ((ck ^ (n & 7)) * 16);
                ldsm4(bf[2*np][0], bf[2*np][1], bf[2*np+1][0], bf[2*np+1][1], sB0 + off);
            }
#pragma unroll
            for (int ms = 0; ms < 2; ms++)
#pragma unroll
                for (int ns = 0; ns < 4; ns++)
                    mma16816h(acc[ms][ns], af[ms], bf[ns]);
        }
        __syncthreads();
    }

    __half* outf = (mode == 0) ? g_qf : (mode == 1) ? g_kf : g_vf;
#pragma unroll
    for (int ms = 0; ms < 2; ms++)
#pragma unroll
        for (int ns = 0; ns < 4; ns++) {
            const int col = bn + wn + ns * 8 + lc * 2;
            const float2 bz = *(const float2*)&bias[col];
#pragma unroll
            for (int hr = 0; hr < 2; hr++) {
                const int row = bm + wm + ms * 16 + lg + hr * 8;
                const float v0 = acc[ms][ns][hr*2+0] + bz.x;
                const float v1 = acc[ms][ns][hr*2+1] + bz.y;
                const int b = row >> 11, s = row & 2047;
                const int h = col >> 6, hd = col & 63;
                const size_t o = (((size_t)(b * H_ + h)) * S_ + s) * HD_ + hd;
                *(__half2*)&outf[o] = __floats2half2_rn(v0, v1);
            }
        }
}

// ---------------------------------------------------------------------------
// 1x-fp16 GEMM for Wo (R14 config): y = A @ Wo^T + bias + resid (fp32 out).
// ---------------------------------------------------------------------------
__global__ void __launch_bounds__(256) gemm_wo(const __half* __restrict__ A,
                                               const __half* __restrict__ W,
                                               const float* __restrict__ bias,
                                               const float* __restrict__ resid)
{
    __shared__ __align__(16) __half sA[2][128*64];
    __shared__ __align__(16) __half sB[2][64*64];

    const int bm = blockIdx.y * 128, bn = blockIdx.x * 64;
    const int tid = threadIdx.x, wid = tid >> 5, lane = tid & 31;
    const int lg = lane >> 2, lc = lane & 3;
    const int wm = (wid >> 1) * 32, wn = (wid & 1) * 32;

    const uint32_t sAb = smem_u32(sA);
    const uint32_t sBb = smem_u32(sB);

    auto prefetch = [&](int k0, int st) {
        const uint32_t a_st = sAb + st * 16384;
        const uint32_t b_st = sBb + st * 8192;
#pragma unroll
        for (int i = 0; i < 4; i++) {
            const int cid = tid + i * 256;
            const int row = cid >> 3, ck = cid & 7;
            const uint32_t so = row * 128 + ((ck ^ (row & 7)) * 16);
            cpasync16(a_st + so, A + (size_t)(bm + row) * D_ + k0 + ck * 8);
        }
#pragma unroll
        for (int i = 0; i < 2; i++) {
            const int cid = tid + i * 256;
            const int row = cid >> 3, ck = cid & 7;
            const uint32_t so = row * 128 + ((ck ^ (row & 7)) * 16);
            cpasync16(b_st + so, W + (size_t)(bn + row) * D_ + k0 + ck * 8);
        }
    };

    float acc[2][4][4] = {};

    prefetch(0, 0); cp_commit();

    const int NIT = D_ / 64;   // 16
    for (int it = 0; it < NIT; it++) {
        if (it + 1 < NIT) { prefetch((it + 1) * 64, (it + 1) & 1); cp_commit(); }
        if (it + 1 < NIT) cp_wait<1>(); else cp_wait<0>();
        __syncthreads();

        const int st = it & 1;
        const uint32_t sA0 = sAb + st * 16384;
        const uint32_t sB0 = sBb + st * 8192;

#pragma unroll
        for (int ks = 0; ks < 4; ks++) {
            uint32_t af[2][4];
            uint32_t bf[4][2];
#pragma unroll
            for (int ms = 0; ms < 2; ms++) {
                const int row = wm + ms * 16 + (lane & 15);
                const int ck = ks * 2 + (lane >> 4);
                const uint32_t off = row * 128 + ((ck ^ (row & 7)) * 16);
                ldsm4(af[ms][0], af[ms][1], af[ms][2], af[ms][3], sA0 + off);
            }
#pragma unroll
            for (int np = 0; np < 2; np++) {
                const int n = wn + np * 16 + (lane & 7) + ((lane >> 4) << 3);
                const int ck = ks * 2 + ((lane >> 3) & 1);
                const uint32_t off = n * 128 + ((ck ^ (n & 7)) * 16);
                ldsm4(bf[2*np][0], bf[2*np][1], bf[2*np+1][0], bf[2*np+1][1], sB0 + off);
            }
#pragma unroll
            for (int ms = 0; ms < 2; ms++)
#pragma unroll
                for (int ns = 0; ns < 4; ns++)
                    mma16816h(acc[ms][ns], af[ms], bf[ns]);
        }
        __syncthreads();
    }

    // epilogue: y = C + bias + resid (fp32)
#pragma unroll
    for (int ms = 0; ms < 2; ms++)
#pragma unroll
        for (int ns = 0; ns < 4; ns++) {
            const int col = bn + wn + ns * 8 + lc * 2;
            const float2 bz = *(const float2*)&bias[col];
#pragma unroll
            for (int hr = 0; hr < 2; hr++) {
                const int row = bm + wm + ms * 16 + lg + hr * 8;
                const size_t o = (size_t)row * D_ + col;
                const float2 rr = *(const float2*)&resid[o];
                float2 w;
                w.x = acc[ms][ns][hr*2+0] + bz.x + rr.x;
                w.y = acc[ms][ns][hr*2+1] + bz.y + rr.y;
                *(float2*)&g_y[o] = w;
            }
        }
}

// ---------------------------------------------------------------------------
// 1x-fp16 flash attention; ex2-based softmax (log2e folded);
// two 32-token half-passes; lane-partial lrow; single-fp16 output.
// dyn smem: sK 2x8KB + sV 2x8KB + maskf 8KB = 40960 B.
// ---------------------------------------------------------------------------
#define SCALE_LOG2E 0.18033688011112042f   // 0.125 * log2(e)

__global__ void __launch_bounds__(128) attn_f16(const int* __restrict__ mask)
{
    extern __shared__ __align__(16) char dynsm[];
    __half* sK = (__half*)dynsm;                    // [2][64*64]
    __half* sV = (__half*)(dynsm + 16384);          // [2][64*64]
    float* smf = (float*)(dynsm + 32768);           // [2048] additive mask (log2 dom.)

    const int bh = blockIdx.y, b = bh >> 4, h = bh & 15;
    const int q0 = blockIdx.x * 64;
    const int tid = threadIdx.x, wid = tid >> 5, lane = tid & 31;
    const int lg = lane >> 2, lc = lane & 3;

    const size_t base = (size_t)bh * S_ * HD_;
    const __half* Qf = g_qf + base;
    const __half* Kf = g_kf + base;
    const __half* Vf = g_vf + base;

    const uint32_t sKb = smem_u32(sK);
    const uint32_t sVb = smem_u32(sV);

    // ---- preload additive mask: 0 or -10000*log2(e) ----
#pragma unroll
    for (int i = 0; i < 4; i++) {
        const int idx = tid + i * 128;
        int4 m = ((const int4*)(mask + b * S_))[idx];
        float4 f;
        f.x = m.x ? 0.f : -14426.95f;
        f.y = m.y ? 0.f : -14426.95f;
        f.z = m.z ? 0.f : -14426.95f;
        f.w = m.w ? 0.f : -14426.95f;
        ((float4*)smf)[idx] = f;
    }

    // ---- stage Q in sK stage0, extract fragments ----
#pragma unroll
    for (int i = 0; i < 4; i++) {
        const int cid = tid + i * 128;
        const int row = cid >> 3, ck = cid & 7;
        const size_t go = (size_t)(q0 + row) * HD_ + ck * 8;
        const uint32_t so = row * 128 + ((ck ^ (row & 7)) * 16);
        *(uint4*)((char*)sK + so) = *(const uint4*)(Qf + go);
    }
    __syncthreads();
    uint32_t qf[4][4];
#pragma unroll
    for (int ks = 0; ks < 4; ks++) {
        const int row = wid * 16 + (lane & 15);
        const int ck = ks * 2 + (lane >> 4);
        const uint32_t off = row * 128 + ((ck ^ (row & 7)) * 16);
        ldsm4(qf[ks][0], qf[ks][1], qf[ks][2], qf[ks][3], sKb + off);
    }
    __syncthreads();

    auto prefetch = [&](int kt, int st) {
#pragma unroll
        for (int i = 0; i < 4; i++) {
            const int cid = tid + i * 128;
            const int row = cid >> 3, ck = cid & 7;
            const size_t go = (size_t)(kt + row) * HD_ + ck * 8;
            const uint32_t so = st * 8192 + row * 128 + ((ck ^ (row & 7)) * 16);
            cpasync16(sKb + so, Kf + go);
            cpasync16(sVb + so, Vf + go);
        }
    };

    float accO[8][4] = {};
    float lrow[2] = {0.f, 0.f};   // lane-partial; reduced at epilogue

    prefetch(0, 0); cp_commit();

    const int NIT = S_ / 64;   // 32
    for (int it = 0; it < NIT; it++) {
        const int kt = it * 64;
        if (it + 1 < NIT) { prefetch((it + 1) * 64, (it + 1) & 1); cp_commit(); }
        if (it + 1 < NIT) cp_wait<1>(); else cp_wait<0>();
        __syncthreads();

        const int st = it & 1;
        const uint32_t sK0 = sKb + st * 8192;
        const uint32_t sV0 = sVb + st * 8192;

        // ---- two 32-token half-passes ----
#pragma unroll
        for (int hf = 0; hf < 2; hf++) {
            float s[4][4] = {};
#pragma unroll
            for (int ks = 0; ks < 4; ks++) {
                uint32_t kb[4][2];
#pragma unroll
                for (int np = 0; np < 2; np++) {
                    const int n = hf * 32 + np * 16 + (lane & 7) + ((lane >> 4) << 3);
                    const int ck = ks * 2 + ((lane >> 3) & 1);
                    const uint32_t off = n * 128 + ((ck ^ (n & 7)) * 16);
                    ldsm4(kb[2*np][0], kb[2*np][1], kb[2*np+1][0], kb[2*np+1][1], sK0 + off);
                }
#pragma unroll
                for (int ns = 0; ns < 4; ns++)
                    mma16816h(s[ns], qf[ks], kb[ns]);
            }

#pragma unroll
            for (int r = 0; r < 2; r++) {
                float ls = 0.f;
#pragma unroll
                for (int ns = 0; ns < 4; ns++)
#pragma unroll
                    for (int j = 0; j < 2; j++) {
                        const float madd = smf[kt + hf*32 + ns*8 + lc*2 + j];
                        const float p = ex2f(fmaf(s[ns][r*2+j], SCALE_LOG2E, madd));
                        s[ns][r*2+j] = p;
                        ls += p;
                    }
                lrow[r] += ls;
            }

#pragma unroll
            for (int j = 0; j < 2; j++) {
                uint32_t pa[4];
                pa[0] = packhf(s[2*j][0],   s[2*j][1]);
                pa[1] = packhf(s[2*j][2],   s[2*j][3]);
                pa[2] = packhf(s[2*j+1][0], s[2*j+1][1]);
                pa[3] = packhf(s[2*j+1][2], s[2*j+1][3]);
                uint32_t vb[8][2];
#pragma unroll
                for (int np = 0; np < 4; np++) {
                    const int tok = hf * 32 + j * 16 + (lane & 15);
                    const int ck = np * 2 + (lane >> 4);
                    const uint32_t off = tok * 128 + ((ck ^ (tok & 7)) * 16);
                    ldsm4t(vb[2*np][0], vb[2*np][1], vb[2*np+1][0], vb[2*np+1][1], sV0 + off);
                }
#pragma unroll
                for (int ns = 0; ns < 8; ns++)
                    mma16816h(accO[ns], pa, vb[ns]);
            }
        }
        __syncthreads();
    }

    // ---- epilogue: reduce lrow, normalize, write single fp16 ----
#pragma unroll
    for (int r = 0; r < 2; r++) {
        lrow[r] += __shfl_xor_sync(0xffffffffu, lrow[r], 1);
        lrow[r] += __shfl_xor_sync(0xffffffffu, lrow[r], 2);
    }
    const float inv0 = 1.f / lrow[0];
    const float inv1 = 1.f / lrow[1];
    const int t0 = b * S_ + q0 + wid * 16 + lg;
#pragma unroll
    for (int ns = 0; ns < 8; ns++) {
        const int col = h * 64 + ns * 8 + lc * 2;
        *(__half2*)&g_af[(size_t)t0 * D_ + col] =
            __floats2half2_rn(accO[ns][0] * inv0, accO[ns][1] * inv0);
        *(__half2*)&g_af[(size_t)(t0 + 8) * D_ + col] =
            __floats2half2_rn(accO[ns][2] * inv1, accO[ns][3] * inv1);
    }
}

// ---------------------------------------------------------------------------
// LayerNorm: one warp per token row. 256 threads = 8 rows/block, no barriers.
// ---------------------------------------------------------------------------
__global__ void __launch_bounds__(256) ln_kernel(const float* __restrict__ gamma,
                                                 const float* __restrict__ beta,
                                                 float* __restrict__ out)
{
    const int row = blockIdx.x * 8 + (threadIdx.x >> 5);
    const int lane = threadIdx.x & 31;
    const float4* yr = (const float4*)(g_y + (size_t)row * D_);

    float4 v[8];
    float sum = 0.f, sq = 0.f;
#pragma unroll
    for (int i = 0; i < 8; i++) {
        v[i] = yr[lane + i * 32];
        sum += v[i].x + v[i].y + v[i].z + v[i].w;
        sq  += v[i].x*v[i].x + v[i].y*v[i].y + v[i].z*v[i].z + v[i].w*v[i].w;
    }
#pragma unroll
    for (int off = 16; off; off >>= 1) {
        sum += __shfl_xor_sync(0xffffffffu, sum, off);
        sq  += __shfl_xor_sync(0xffffffffu, sq,  off);
    }
    const float mu   = sum * (1.f / D_);
    const float var  = sq * (1.f / D_) - mu * mu;
    const float rstd = rsqrtf(var + 1e-5f);

    float4* outr = (float4*)(out + (size_t)row * D_);
#pragma unroll
    for (int i = 0; i < 8; i++) {
        const float4 g4 = ((const float4*)gamma)[lane + i * 32];
        const float4 b4 = ((const float4*)beta)[lane + i * 32];
        float4 r;
        r.x = (v[i].x - mu) * rstd * g4.x + b4.x;
        r.y = (v[i].y - mu) * rstd * g4.y + b4.y;
        r.z = (v[i].z - mu) * rstd * g4.z + b4.z;
        r.w = (v[i].w - mu) * rstd * g4.w + b4.w;
        outr[lane + i * 32] = r;
    }
}

// ---------------------------------------------------------------------------
extern "C" void kernel_launch(void* const* d_in, const int* in_sizes, int n_in,
                              void* d_out, int out_size)
{
    const float* x     = (const float*)d_in[0];
    // d_in[1]: template_ids (unused by reference math)
    const int*   mask  = (const int*)  d_in[2];
    const float* Wq    = (const float*)d_in[3];
    const float* bq    = (const float*)d_in[4];
    const float* Wk    = (const float*)d_in[5];
    const float* bk    = (const float*)d_in[6];
    const float* Wv    = (const float*)d_in[7];
    const float* bv    = (const float*)d_in[8];
    const float* Wo    = (const float*)d_in[9];
    const float* bo    = (const float*)d_in[10];
    const float* gamma = (const float*)d_in[11];
    const float* beta  = (const float*)d_in[12];
    float* out = (float*)d_out;

    __half *xf, *wf, *af;
    cudaGetSymbolAddress((void**)&xf, g_xf);
    cudaGetSymbolAddress((void**)&wf, g_wf);
    cudaGetSymbolAddress((void**)&af, g_af);

    tof16_kernel<<<M_*D_/4/256, 256>>>(x, xf, M_*D_/4);
    splitw_kernel<<<dim3(D_*D_/4/256, 4), 256>>>(Wq, Wk, Wv, Wo);

    gemm_f16<<<dim3(D_/64, M_/128, 3), 256>>>(xf, bq, bk, bv);

    const int attn_smem = 40960;
    cudaFuncSetAttribute(attn_f16, cudaFuncAttributeMaxDynamicSharedMemorySize, attn_smem);
    attn_f16<<<dim3(S_/64, B_*H_), 128, attn_smem>>>(mask);

    gemm_wo<<<dim3(D_/64, M_/128), 256>>>(af, wf + 3*(size_t)D_*D_, bo, x);
    ln_kernel<<<M_/8, 256>>>(gamma, beta, out);
}

// round 17
// speedup vs baseline: 1.0543x; 1.0318x over previous
#include <cuda_runtime.h>
#include <cuda_bf16.h>
#include <cuda_fp16.h>
#include <math.h>
#include <stdint.h>

#define B_  4
#define S_  2048
#define D_  1024
#define H_  16
#define HD_ 64
#define M_  (B_*S_)   // 8192 tokens

#define SCALE_LOG2E 0.18033688011112042f   // 0.125 * log2(e)

// ---------------------------------------------------------------------------
// Scratch (device globals; no runtime allocation)
// ---------------------------------------------------------------------------
__device__ __half g_xf[M_*D_];                          // x fp16 [M][D]
__device__ __half g_wf[4*D_*D_];                        // Wq,Wk,Wv,Wo fp16 [N][K]
__device__ __half g_qf[M_*D_];                          // q (pre-scaled by 0.125*log2e)
__device__ __half g_kf[M_*D_];
__device__ __half g_vf[M_*D_];
__device__ __half g_af[M_*D_];                          // attn out fp16 [M][D]
__device__ float g_y[M_*D_];                            // pre-LN fp32

// ---------------------------------------------------------------------------
// Helpers
// ---------------------------------------------------------------------------
__device__ __forceinline__ uint32_t packhf(float a, float b) {
    __half2 t = __floats2half2_rn(a, b);
    return *reinterpret_cast<uint32_t*>(&t);
}
__device__ __forceinline__ uint32_t ex2h2(uint32_t x) {
    uint32_t r;
    asm("ex2.approx.f16x2 %0, %1;" : "=r"(r) : "r"(x));
    return r;
}
__device__ __forceinline__ void ldsm4(uint32_t& r0, uint32_t& r1, uint32_t& r2, uint32_t& r3,
                                      uint32_t a) {
    asm volatile("ldmatrix.sync.aligned.m8n8.x4.shared.b16 {%0,%1,%2,%3},[%4];"
                 : "=r"(r0), "=r"(r1), "=r"(r2), "=r"(r3) : "r"(a));
}
__device__ __forceinline__ void ldsm4t(uint32_t& r0, uint32_t& r1, uint32_t& r2, uint32_t& r3,
                                       uint32_t a) {
    asm volatile("ldmatrix.sync.aligned.m8n8.x4.trans.shared.b16 {%0,%1,%2,%3},[%4];"
                 : "=r"(r0), "=r"(r1), "=r"(r2), "=r"(r3) : "r"(a));
}
__device__ __forceinline__ void mma16816h(float* d, const uint32_t* a, const uint32_t* b) {
    asm volatile(
        "mma.sync.aligned.m16n8k16.row.col.f32.f16.f16.f32 "
        "{%0,%1,%2,%3},{%4,%5,%6,%7},{%8,%9},{%0,%1,%2,%3};"
        : "+f"(d[0]), "+f"(d[1]), "+f"(d[2]), "+f"(d[3])
        : "r"(a[0]), "r"(a[1]), "r"(a[2]), "r"(a[3]), "r"(b[0]), "r"(b[1]));
}
__device__ __forceinline__ void cpasync16(uint32_t dst, const void* src) {
    asm volatile("cp.async.cg.shared.global [%0], [%1], 16;" :: "r"(dst), "l"(src));
}
__device__ __forceinline__ void cp_commit() {
    asm volatile("cp.async.commit_group;" ::: "memory");
}
template<int N> __device__ __forceinline__ void cp_wait() {
    asm volatile("cp.async.wait_group %0;" :: "n"(N) : "memory");
}
__device__ __forceinline__ uint32_t smem_u32(const void* p) {
    return (uint32_t)__cvta_generic_to_shared(p);
}

// ---------------------------------------------------------------------------
// Conversion kernels
// ---------------------------------------------------------------------------
__global__ void __launch_bounds__(256) tof16_kernel(const float* __restrict__ src,
                                                    __half* __restrict__ dst, int n4)
{
    int i = blockIdx.x * 256 + threadIdx.x;
    if (i >= n4) return;
    float4 v = ((const float4*)src)[i];
    ((__half2*)dst)[i*2]   = __floats2half2_rn(v.x, v.y);
    ((__half2*)dst)[i*2+1] = __floats2half2_rn(v.z, v.w);
}

__global__ void __launch_bounds__(256) splitw_kernel(const float* __restrict__ w0,
                                                     const float* __restrict__ w1,
                                                     const float* __restrict__ w2,
                                                     const float* __restrict__ w3)
{
    const int wsel = blockIdx.y;
    const float* src = (wsel == 0) ? w0 : (wsel == 1) ? w1 : (wsel == 2) ? w2 : w3;
    __half* dst = g_wf + (size_t)wsel * D_ * D_;
    int i = blockIdx.x * 256 + threadIdx.x;
    float4 v = ((const float4*)src)[i];
    ((__half2*)dst)[i*2]   = __floats2half2_rn(v.x, v.y);
    ((__half2*)dst)[i*2+1] = __floats2half2_rn(v.z, v.w);
}

// ---------------------------------------------------------------------------
// 1x-fp16 GEMM for Q/K/V projections, merged via blockIdx.z.
// CTA 128x64, BK=64, 8 warps (warp 32x32). 2-stage cp.async. 48KB static smem.
// mode 0 (Q) output is pre-scaled by 0.125*log2(e) for the ex2 softmax.
// ---------------------------------------------------------------------------
__global__ void __launch_bounds__(256) gemm_f16(const __half* __restrict__ X,
                                                const float* __restrict__ bq,
                                                const float* __restrict__ bk,
                                                const float* __restrict__ bv)
{
    __shared__ __align__(16) __half sA[2][128*64];   // 16KB/stage
    __shared__ __align__(16) __half sB[2][64*64];    // 8KB/stage

    const int mode = blockIdx.z;
    const __half* W = g_wf + (size_t)mode * D_ * D_;
    const float* bias = (mode == 0) ? bq : (mode == 1) ? bk : bv;
    const float qsc = (mode == 0) ? SCALE_LOG2E : 1.0f;

    const int bm = blockIdx.y * 128, bn = blockIdx.x * 64;
    const int tid = threadIdx.x, wid = tid >> 5, lane = tid & 31;
    const int lg = lane >> 2, lc = lane & 3;
    const int wm = (wid >> 1) * 32, wn = (wid & 1) * 32;

    const uint32_t sAb = smem_u32(sA);
    const uint32_t sBb = smem_u32(sB);

    auto prefetch = [&](int k0, int st) {
        const uint32_t a_st = sAb + st * 16384;
        const uint32_t b_st = sBb + st * 8192;
#pragma unroll
        for (int i = 0; i < 4; i++) {
            const int cid = tid + i * 256;
            const int row = cid >> 3, ck = cid & 7;
            const uint32_t so = row * 128 + ((ck ^ (row & 7)) * 16);
            cpasync16(a_st + so, X + (size_t)(bm + row) * D_ + k0 + ck * 8);
        }
#pragma unroll
        for (int i = 0; i < 2; i++) {
            const int cid = tid + i * 256;
            const int row = cid >> 3, ck = cid & 7;
            const uint32_t so = row * 128 + ((ck ^ (row & 7)) * 16);
            cpasync16(b_st + so, W + (size_t)(bn + row) * D_ + k0 + ck * 8);
        }
    };

    float acc[2][4][4] = {};

    prefetch(0, 0); cp_commit();

    const int NIT = D_ / 64;   // 16
    for (int it = 0; it < NIT; it++) {
        if (it + 1 < NIT) { prefetch((it + 1) * 64, (it + 1) & 1); cp_commit(); }
        if (it + 1 < NIT) cp_wait<1>(); else cp_wait<0>();
        __syncthreads();

        const int st = it & 1;
        const uint32_t sA0 = sAb + st * 16384;
        const uint32_t sB0 = sBb + st * 8192;

#pragma unroll
        for (int ks = 0; ks < 4; ks++) {
            uint32_t af[2][4];
            uint32_t bf[4][2];
#pragma unroll
            for (int ms = 0; ms < 2; ms++) {
                const int row = wm + ms * 16 + (lane & 15);
                const int ck = ks * 2 + (lane >> 4);
                const uint32_t off = row * 128 + ((ck ^ (row & 7)) * 16);
                ldsm4(af[ms][0], af[ms][1], af[ms][2], af[ms][3], sA0 + off);
            }
#pragma unroll
            for (int np = 0; np < 2; np++) {
                const int n = wn + np * 16 + (lane & 7) + ((lane >> 4) << 3);
                const int ck = ks * 2 + ((lane >> 3) & 1);
                const uint32_t off = n * 128 + ((ck ^ (n & 7)) * 16);
                ldsm4(bf[2*np][0], bf[2*np][1], bf[2*np+1][0], bf[2*np+1][1], sB0 + off);
            }
#pragma unroll
            for (int ms = 0; ms < 2; ms++)
#pragma unroll
                for (int ns = 0; ns < 4; ns++)
                    mma16816h(acc[ms][ns], af[ms], bf[ns]);
        }
        __syncthreads();
    }

    __half* outf = (mode == 0) ? g_qf : (mode == 1) ? g_kf : g_vf;
#pragma unroll
    for (int ms = 0; ms < 2; ms++)
#pragma unroll
        for (int ns = 0; ns < 4; ns++) {
            const int col = bn + wn + ns * 8 + lc * 2;
            const float2 bz = *(const float2*)&bias[col];
#pragma unroll
            for (int hr = 0; hr < 2; hr++) {
                const int row = bm + wm + ms * 16 + lg + hr * 8;
                const float v0 = (acc[ms][ns][hr*2+0] + bz.x) * qsc;
                const float v1 = (acc[ms][ns][hr*2+1] + bz.y) * qsc;
                const int b = row >> 11, s = row & 2047;
                const int h = col >> 6, hd = col & 63;
                const size_t o = (((size_t)(b * H_ + h)) * S_ + s) * HD_ + hd;
                *(__half2*)&outf[o] = __floats2half2_rn(v0, v1);
            }
        }
}

// ---------------------------------------------------------------------------
// 1x-fp16 GEMM for Wo: y = A @ Wo^T + bias + resid (fp32 out).
// ---------------------------------------------------------------------------
__global__ void __launch_bounds__(256) gemm_wo(const __half* __restrict__ A,
                                               const __half* __restrict__ W,
                                               const float* __restrict__ bias,
                                               const float* __restrict__ resid)
{
    __shared__ __align__(16) __half sA[2][128*64];
    __shared__ __align__(16) __half sB[2][64*64];

    const int bm = blockIdx.y * 128, bn = blockIdx.x * 64;
    const int tid = threadIdx.x, wid = tid >> 5, lane = tid & 31;
    const int lg = lane >> 2, lc = lane & 3;
    const int wm = (wid >> 1) * 32, wn = (wid & 1) * 32;

    const uint32_t sAb = smem_u32(sA);
    const uint32_t sBb = smem_u32(sB);

    auto prefetch = [&](int k0, int st) {
        const uint32_t a_st = sAb + st * 16384;
        const uint32_t b_st = sBb + st * 8192;
#pragma unroll
        for (int i = 0; i < 4; i++) {
            const int cid = tid + i * 256;
            const int row = cid >> 3, ck = cid & 7;
            const uint32_t so = row * 128 + ((ck ^ (row & 7)) * 16);
            cpasync16(a_st + so, A + (size_t)(bm + row) * D_ + k0 + ck * 8);
        }
#pragma unroll
        for (int i = 0; i < 2; i++) {
            const int cid = tid + i * 256;
            const int row = cid >> 3, ck = cid & 7;
            const uint32_t so = row * 128 + ((ck ^ (row & 7)) * 16);
            cpasync16(b_st + so, W + (size_t)(bn + row) * D_ + k0 + ck * 8);
        }
    };

    float acc[2][4][4] = {};

    prefetch(0, 0); cp_commit();

    const int NIT = D_ / 64;   // 16
    for (int it = 0; it < NIT; it++) {
        if (it + 1 < NIT) { prefetch((it + 1) * 64, (it + 1) & 1); cp_commit(); }
        if (it + 1 < NIT) cp_wait<1>(); else cp_wait<0>();
        __syncthreads();

        const int st = it & 1;
        const uint32_t sA0 = sAb + st * 16384;
        const uint32_t sB0 = sBb + st * 8192;

#pragma unroll
        for (int ks = 0; ks < 4; ks++) {
            uint32_t af[2][4];
            uint32_t bf[4][2];
#pragma unroll
            for (int ms = 0; ms < 2; ms++) {
                const int row = wm + ms * 16 + (lane & 15);
                const int ck = ks * 2 + (lane >> 4);
                const uint32_t off = row * 128 + ((ck ^ (row & 7)) * 16);
                ldsm4(af[ms][0], af[ms][1], af[ms][2], af[ms][3], sA0 + off);
            }
#pragma unroll
            for (int np = 0; np < 2; np++) {
                const int n = wn + np * 16 + (lane & 7) + ((lane >> 4) << 3);
                const int ck = ks * 2 + ((lane >> 3) & 1);
                const uint32_t off = n * 128 + ((ck ^ (n & 7)) * 16);
                ldsm4(bf[2*np][0], bf[2*np][1], bf[2*np+1][0], bf[2*np+1][1], sB0 + off);
            }
#pragma unroll
            for (int ms = 0; ms < 2; ms++)
#pragma unroll
                for (int ns = 0; ns < 4; ns++)
                    mma16816h(acc[ms][ns], af[ms], bf[ns]);
        }
        __syncthreads();
    }

    // epilogue: y = C + bias + resid (fp32)
#pragma unroll
    for (int ms = 0; ms < 2; ms++)
#pragma unroll
        for (int ns = 0; ns < 4; ns++) {
            const int col = bn + wn + ns * 8 + lc * 2;
            const float2 bz = *(const float2*)&bias[col];
#pragma unroll
            for (int hr = 0; hr < 2; hr++) {
                const int row = bm + wm + ms * 16 + lg + hr * 8;
                const size_t o = (size_t)row * D_ + col;
                const float2 rr = *(const float2*)&resid[o];
                float2 w;
                w.x = acc[ms][ns][hr*2+0] + bz.x + rr.x;
                w.y = acc[ms][ns][hr*2+1] + bz.y + rr.y;
                *(float2*)&g_y[o] = w;
            }
        }
}

// ---------------------------------------------------------------------------
// 1x-fp16 flash attention; packed fp16 ex2 softmax (scale pre-folded into Q);
// two 32-token half-passes; lane-partial lrow; single-fp16 output.
// dyn smem: sK 2x8KB + sV 2x8KB + maskf 8KB = 40960 B.
// ---------------------------------------------------------------------------
__global__ void __launch_bounds__(128) attn_f16(const int* __restrict__ mask)
{
    extern __shared__ __align__(16) char dynsm[];
    __half* sK = (__half*)dynsm;                    // [2][64*64]
    __half* sV = (__half*)(dynsm + 16384);          // [2][64*64]
    float* smf = (float*)(dynsm + 32768);           // [2048] additive mask (log2 dom.)

    const int bh = blockIdx.y, b = bh >> 4, h = bh & 15;
    const int q0 = blockIdx.x * 64;
    const int tid = threadIdx.x, wid = tid >> 5, lane = tid & 31;
    const int lg = lane >> 2, lc = lane & 3;

    const size_t base = (size_t)bh * S_ * HD_;
    const __half* Qf = g_qf + base;
    const __half* Kf = g_kf + base;
    const __half* Vf = g_vf + base;

    const uint32_t sKb = smem_u32(sK);
    const uint32_t sVb = smem_u32(sV);

    // ---- preload additive mask: 0 or -10000*log2(e) ----
#pragma unroll
    for (int i = 0; i < 4; i++) {
        const int idx = tid + i * 128;
        int4 m = ((const int4*)(mask + b * S_))[idx];
        float4 f;
        f.x = m.x ? 0.f : -14426.95f;
        f.y = m.y ? 0.f : -14426.95f;
        f.z = m.z ? 0.f : -14426.95f;
        f.w = m.w ? 0.f : -14426.95f;
        ((float4*)smf)[idx] = f;
    }

    // ---- stage Q in sK stage0, extract fragments ----
#pragma unroll
    for (int i = 0; i < 4; i++) {
        const int cid = tid + i * 128;
        const int row = cid >> 3, ck = cid & 7;
        const size_t go = (size_t)(q0 + row) * HD_ + ck * 8;
        const uint32_t so = row * 128 + ((ck ^ (row & 7)) * 16);
        *(uint4*)((char*)sK + so) = *(const uint4*)(Qf + go);
    }
    __syncthreads();
    uint32_t qf[4][4];
#pragma unroll
    for (int ks = 0; ks < 4; ks++) {
        const int row = wid * 16 + (lane & 15);
        const int ck = ks * 2 + (lane >> 4);
        const uint32_t off = row * 128 + ((ck ^ (row & 7)) * 16);
        ldsm4(qf[ks][0], qf[ks][1], qf[ks][2], qf[ks][3], sKb + off);
    }
    __syncthreads();

    auto prefetch = [&](int kt, int st) {
#pragma unroll
        for (int i = 0; i < 4; i++) {
            const int cid = tid + i * 128;
            const int row = cid >> 3, ck = cid & 7;
            const size_t go = (size_t)(kt + row) * HD_ + ck * 8;
            const uint32_t so = st * 8192 + row * 128 + ((ck ^ (row & 7)) * 16);
            cpasync16(sKb + so, Kf + go);
            cpasync16(sVb + so, Vf + go);
        }
    };

    float accO[8][4] = {};
    float lrow[2] = {0.f, 0.f};   // lane-partial; reduced at epilogue

    prefetch(0, 0); cp_commit();

    const int NIT = S_ / 64;   // 32
    for (int it = 0; it < NIT; it++) {
        const int kt = it * 64;
        if (it + 1 < NIT) { prefetch((it + 1) * 64, (it + 1) & 1); cp_commit(); }
        if (it + 1 < NIT) cp_wait<1>(); else cp_wait<0>();
        __syncthreads();

        const int st = it & 1;
        const uint32_t sK0 = sKb + st * 8192;
        const uint32_t sV0 = sVb + st * 8192;

        // ---- two 32-token half-passes ----
#pragma unroll
        for (int hf = 0; hf < 2; hf++) {
            float s[4][4] = {};
#pragma unroll
            for (int ks = 0; ks < 4; ks++) {
                uint32_t kb[4][2];
#pragma unroll
                for (int np = 0; np < 2; np++) {
                    const int n = hf * 32 + np * 16 + (lane & 7) + ((lane >> 4) << 3);
                    const int ck = ks * 2 + ((lane >> 3) & 1);
                    const uint32_t off = n * 128 + ((ck ^ (n & 7)) * 16);
                    ldsm4(kb[2*np][0], kb[2*np][1], kb[2*np+1][0], kb[2*np+1][1], sK0 + off);
                }
#pragma unroll
                for (int ns = 0; ns < 4; ns++)
                    mma16816h(s[ns], qf[ks], kb[ns]);
            }

            // ---- softmax numerator: p = ex2(s + madd), packed fp16 ----
            uint32_t pp[4][2];   // [ns][r] packed half2 probabilities
#pragma unroll
            for (int ns = 0; ns < 4; ns++) {
                const int kb0 = kt + hf*32 + ns*8 + lc*2;
                const float m0 = smf[kb0], m1 = smf[kb0 + 1];
#pragma unroll
                for (int r = 0; r < 2; r++)
                    pp[ns][r] = ex2h2(packhf(s[ns][r*2+0] + m0, s[ns][r*2+1] + m1));
            }
#pragma unroll
            for (int r = 0; r < 2; r++) {
                __half2 hs = __hadd2(__hadd2(*(__half2*)&pp[0][r], *(__half2*)&pp[1][r]),
                                     __hadd2(*(__half2*)&pp[2][r], *(__half2*)&pp[3][r]));
                float2 f = __half22float2(hs);
                lrow[r] += f.x + f.y;
            }

            // ---- O += P @ V (pp is already the packed A fragment) ----
#pragma unroll
            for (int j = 0; j < 2; j++) {
                uint32_t pa[4] = {pp[2*j][0], pp[2*j][1], pp[2*j+1][0], pp[2*j+1][1]};
                uint32_t vb[8][2];
#pragma unroll
                for (int np = 0; np < 4; np++) {
                    const int tok = hf * 32 + j * 16 + (lane & 15);
                    const int ck = np * 2 + (lane >> 4);
                    const uint32_t off = tok * 128 + ((ck ^ (tok & 7)) * 16);
                    ldsm4t(vb[2*np][0], vb[2*np][1], vb[2*np+1][0], vb[2*np+1][1], sV0 + off);
                }
#pragma unroll
                for (int ns = 0; ns < 8; ns++)
                    mma16816h(accO[ns], pa, vb[ns]);
            }
        }
        __syncthreads();
    }

    // ---- epilogue: reduce lrow, normalize, write single fp16 ----
#pragma unroll
    for (int r = 0; r < 2; r++) {
        lrow[r] += __shfl_xor_sync(0xffffffffu, lrow[r], 1);
        lrow[r] += __shfl_xor_sync(0xffffffffu, lrow[r], 2);
    }
    const float inv0 = 1.f / lrow[0];
    const float inv1 = 1.f / lrow[1];
    const int t0 = b * S_ + q0 + wid * 16 + lg;
#pragma unroll
    for (int ns = 0; ns < 8; ns++) {
        const int col = h * 64 + ns * 8 + lc * 2;
        *(__half2*)&g_af[(size_t)t0 * D_ + col] =
            __floats2half2_rn(accO[ns][0] * inv0, accO[ns][1] * inv0);
        *(__half2*)&g_af[(size_t)(t0 + 8) * D_ + col] =
            __floats2half2_rn(accO[ns][2] * inv1, accO[ns][3] * inv1);
    }
}

// ---------------------------------------------------------------------------
// LayerNorm: one warp per token row. 256 threads = 8 rows/block, no barriers.
// ---------------------------------------------------------------------------
__global__ void __launch_bounds__(256) ln_kernel(const float* __restrict__ gamma,
                                                 const float* __restrict__ beta,
                                                 float* __restrict__ out)
{
    const int row = blockIdx.x * 8 + (threadIdx.x >> 5);
    const int lane = threadIdx.x & 31;
    const float4* yr = (const float4*)(g_y + (size_t)row * D_);

    float4 v[8];
    float sum = 0.f, sq = 0.f;
#pragma unroll
    for (int i = 0; i < 8; i++) {
        v[i] = yr[lane + i * 32];
        sum += v[i].x + v[i].y + v[i].z + v[i].w;
        sq  += v[i].x*v[i].x + v[i].y*v[i].y + v[i].z*v[i].z + v[i].w*v[i].w;
    }
#pragma unroll
    for (int off = 16; off; off >>= 1) {
        sum += __shfl_xor_sync(0xffffffffu, sum, off);
        sq  += __shfl_xor_sync(0xffffffffu, sq,  off);
    }
    const float mu   = sum * (1.f / D_);
    const float var  = sq * (1.f / D_) - mu * mu;
    const float rstd = rsqrtf(var + 1e-5f);

    float4* outr = (float4*)(out + (size_t)row * D_);
#pragma unroll
    for (int i = 0; i < 8; i++) {
        const float4 g4 = ((const float4*)gamma)[lane + i * 32];
        const float4 b4 = ((const float4*)beta)[lane + i * 32];
        float4 r;
        r.x = (v[i].x - mu) * rstd * g4.x + b4.x;
        r.y = (v[i].y - mu) * rstd * g4.y + b4.y;
        r.z = (v[i].z - mu) * rstd * g4.z + b4.z;
        r.w = (v[i].w - mu) * rstd * g4.w + b4.w;
        outr[lane + i * 32] = r;
    }
}

// ---------------------------------------------------------------------------
extern "C" void kernel_launch(void* const* d_in, const int* in_sizes, int n_in,
                              void* d_out, int out_size)
{
    const float* x     = (const float*)d_in[0];
    // d_in[1]: template_ids (unused by reference math)
    const int*   mask  = (const int*)  d_in[2];
    const float* Wq    = (const float*)d_in[3];
    const float* bq    = (const float*)d_in[4];
    const float* Wk    = (const float*)d_in[5];
    const float* bk    = (const float*)d_in[6];
    const float* Wv    = (const float*)d_in[7];
    const float* bv    = (const float*)d_in[8];
    const float* Wo    = (const float*)d_in[9];
    const float* bo    = (const float*)d_in[10];
    const float* gamma = (const float*)d_in[11];
    const float* beta  = (const float*)d_in[12];
    float* out = (float*)d_out;

    __half *xf, *wf, *af;
    cudaGetSymbolAddress((void**)&xf, g_xf);
    cudaGetSymbolAddress((void**)&wf, g_wf);
    cudaGetSymbolAddress((void**)&af, g_af);

    tof16_kernel<<<M_*D_/4/256, 256>>>(x, xf, M_*D_/4);
    splitw_kernel<<<dim3(D_*D_/4/256, 4), 256>>>(Wq, Wk, Wv, Wo);

    gemm_f16<<<dim3(D_/64, M_/128, 3), 256>>>(xf, bq, bk, bv);

    const int attn_smem = 40960;
    cudaFuncSetAttribute(attn_f16, cudaFuncAttributeMaxDynamicSharedMemorySize, attn_smem);
    attn_f16<<<dim3(S_/64, B_*H_), 128, attn_smem>>>(mask);

    gemm_wo<<<dim3(D_/64, M_/128), 256>>>(af, wf + 3*(size_t)D_*D_, bo, x);
    ln_kernel<<<M_/8, 256>>>(gamma, beta, out);
}